// round 13
// baseline (speedup 1.0000x reference)
#include <cuda_runtime.h>
#include <cuda_fp16.h>
#include <cstdint>
#include <math.h>

#define MAXN   4096
#define MAXD   512
#define NB     1024
#define MARGIN 0.3f
#define BIGD2  3.0e38f

// ---------------- scratch ----------------
__device__ __align__(16) __half g_Ehi[MAXN * MAXD];
__device__ float    g_sq[MAXN];
__device__ float    g_hp2[MAXN];
__device__ float    g_hpB2[MAXN];
__device__ unsigned g_hnfb[MAXN];
__device__ unsigned g_hnsemi[MAXN];
__device__ int      g_semiflag;
__device__ int      g_ccount[NB];
__device__ int      g_coff[NB];
__device__ int      g_clist[MAXN];

__device__ __forceinline__ uint32_t smem_u32(const void* p) {
    uint32_t a;
    asm("{ .reg .u64 t; cvta.to.shared.u64 t, %1; cvt.u32.u64 %0, t; }" : "=r"(a) : "l"(p));
    return a;
}

#define CP_ASYNC16(dst, src) \
    asm volatile("cp.async.cg.shared.global [%0], [%1], 16;" :: "r"(dst), "l"(src))
#define CP_COMMIT() asm volatile("cp.async.commit_group;")
#define CP_WAIT2()  asm volatile("cp.async.wait_group 2;")
#define CP_WAIT1()  asm volatile("cp.async.wait_group 1;")
#define CP_WAIT0()  asm volatile("cp.async.wait_group 0;")

#define LDM4(r0, r1, r2, r3, addr)                                              \
    asm volatile("ldmatrix.sync.aligned.m8n8.x4.shared.b16 {%0,%1,%2,%3}, [%4];" \
        : "=r"(r0), "=r"(r1), "=r"(r2), "=r"(r3) : "r"(addr))

#define MMA16816(c, a, b0, b1)                                                   \
    asm volatile("mma.sync.aligned.m16n8k16.row.col.f32.f16.f16.f32 "            \
        "{%0,%1,%2,%3},{%4,%5,%6,%7},{%8,%9},{%0,%1,%2,%3};"                     \
        : "+f"((c)[0]), "+f"((c)[1]), "+f"((c)[2]), "+f"((c)[3])                 \
        : "r"((a)[0]), "r"((a)[1]), "r"((a)[2]), "r"((a)[3]), "r"(b0), "r"(b1))

// ---------------- kernel 0: convert + row sq + per-row init (warp per row) ----------
__global__ void convsq_kernel(const float* __restrict__ E, int d) {
    int wid = threadIdx.x >> 5, lane = threadIdx.x & 31;
    int row = blockIdx.x * 8 + wid;
    const float4* p = (const float4*)(E + (size_t)row * d);
    int d4 = d >> 2;                      // 128
    float s = 0.f;
    for (int c = lane; c < d4; c += 32) {
        float4 v = p[c];
        s += v.x * v.x + v.y * v.y + v.z * v.z + v.w * v.w;
        __half2 h01 = __halves2half2(__float2half(v.x), __float2half(v.y));
        __half2 h23 = __halves2half2(__float2half(v.z), __float2half(v.w));
        size_t o = (size_t)row * d + 4 * c;
        *(__half2*)(g_Ehi + o) = h01;
        *(__half2*)(g_Ehi + o + 2) = h23;
    }
    for (int o = 16; o; o >>= 1) s += __shfl_xor_sync(0xffffffffu, s, o);
    if (lane == 0) {
        g_sq[row] = s;
        g_hnfb[row] = 0u;
        g_hnsemi[row] = __float_as_uint(BIGD2);
        if (row == 0) g_semiflag = 0;
    }
}

// ---------------- kernel 1: hist + hierarchical scan + fill (single block) ----------
__global__ void classlist_kernel(const int* __restrict__ labels, int n) {
    __shared__ int cnt[NB];
    __shared__ int cur[NB];
    __shared__ int wsum[32];
    int t = threadIdx.x;                  // 1024 threads
    int lane = t & 31, w = t >> 5;
    cnt[t] = 0;
    __syncthreads();
    for (int i = t; i < n; i += blockDim.x) atomicAdd(&cnt[labels[i] & (NB - 1)], 1);
    __syncthreads();
    int v = cnt[t];
    // warp inclusive scan
    int x = v;
#pragma unroll
    for (int o = 1; o < 32; o <<= 1) {
        int u = __shfl_up_sync(0xffffffffu, x, o);
        if (lane >= o) x += u;
    }
    if (lane == 31) wsum[w] = x;
    __syncthreads();
    if (w == 0) {
        int y = wsum[lane];
#pragma unroll
        for (int o = 1; o < 32; o <<= 1) {
            int u = __shfl_up_sync(0xffffffffu, y, o);
            if (lane >= o) y += u;
        }
        wsum[lane] = y;
    }
    __syncthreads();
    int incl = x + (w > 0 ? wsum[w - 1] : 0);
    int excl = incl - v;
    g_coff[t] = excl;
    g_ccount[t] = v;
    cur[t] = excl;
    __syncthreads();
    for (int i = t; i < n; i += blockDim.x) {
        int c = labels[i] & (NB - 1);
        int pos = atomicAdd(&cur[c], 1);
        g_clist[pos] = i;
    }
}

// ------- kernel 2: exact fp32 hardest positive (block per anchor, 8 warps) ----------
__global__ void hp_kernel(const float* __restrict__ E, const int* __restrict__ labels,
                          int n, int d) {
    int anchor = blockIdx.x;
    int lid = threadIdx.x & 31, wid = threadIdx.x >> 5;   // 8 warps
    int c = labels[anchor] & (NB - 1);
    const float4* ea = (const float4*)(E + (size_t)anchor * d);
    int dk4 = d >> 7;
    float4 a0[MAXD / 128];
#pragma unroll
    for (int j = 0; j < MAXD / 128; j++) if (j < dk4) a0[j] = ea[lid + 32 * j];
    int beg = g_coff[c], cnt = g_ccount[c];
    float sqa = g_sq[anchor];
    float maxd2 = 0.f;
    for (int t = wid; t < cnt; t += 8) {
        int m = g_clist[beg + t];
        const float4* em = (const float4*)(E + (size_t)m * d);
        float dot = 0.f;
#pragma unroll
        for (int j = 0; j < MAXD / 128; j++)
            if (j < dk4) {
                float4 b = em[lid + 32 * j];
                dot += a0[j].x * b.x + a0[j].y * b.y + a0[j].z * b.z + a0[j].w * b.w;
            }
        for (int o = 16; o; o >>= 1) dot += __shfl_xor_sync(0xffffffffu, dot, o);
        float d2 = sqa + g_sq[m] - 2.f * dot;
        maxd2 = fmaxf(maxd2, d2);
    }
    __shared__ float wmax[8];
    if (lid == 0) wmax[wid] = maxd2;
    __syncthreads();
    if (threadIdx.x == 0) {
        float h2 = 1e-12f;
#pragma unroll
        for (int k = 0; k < 8; k++) h2 = fmaxf(h2, wmax[k]);
        g_hp2[anchor] = h2;
        float hp = sqrtf(h2);
        g_hpB2[anchor] = (hp + MARGIN) * (hp + MARGIN);
    }
}

// ------- kernel 3: HMMA GEMM, BK=64 (128B rows), 4-stage pipeline, 8 chunks ---------
#define BK      64
#define TILEB   16384
#define STAGEB  (2 * TILEB)
#define NSTAGE  4
#define AUXO    (NSTAGE * STAGEB)
#define SMEM_DYN (AUXO + 6144)

__device__ __forceinline__ uint32_t swz(int r, int ch) {
    return (uint32_t)(r * 128 + ((ch ^ (r & 7)) << 4));
}

__global__ __launch_bounds__(512, 1) void gemm_kernel(const int* __restrict__ labels,
                                                      int n, int d) {
    extern __shared__ char sm[];
    uint32_t sb = smem_u32(sm);
    int tid = threadIdx.x, lane = tid & 31, wid = tid >> 5;
    int wm = wid >> 2, wn = wid & 3;

    int bid = blockIdx.x;
    int by = (int)((sqrtf(8.f * (float)bid + 1.f) - 1.f) * 0.5f);
    while ((by + 1) * (by + 2) / 2 <= bid) by++;
    while (by * (by + 1) / 2 > bid) by--;
    int bx = bid - by * (by + 1) / 2;
    int rowBase = by * 128, colBase = bx * 128;
    bool diag = (bx == by);

    float*    s_sqc  = (float*)(sm + AUXO);
    int*      s_labc = (int*)(sm + AUXO + 512);
    float*    s_sqr  = (float*)(sm + AUXO + 1024);
    int*      s_labr = (int*)(sm + AUXO + 1536);
    float*    s_hp2r = (float*)(sm + AUXO + 2048);
    float*    s_hpBr = (float*)(sm + AUXO + 2560);
    float*    s_hp2c = (float*)(sm + AUXO + 3072);
    float*    s_hpBc = (float*)(sm + AUXO + 3584);
    unsigned* shRmax = (unsigned*)(sm + AUXO + 4096);
    unsigned* shRmin = (unsigned*)(sm + AUXO + 4608);
    unsigned* shCmax = (unsigned*)(sm + AUXO + 5120);
    unsigned* shCmin = (unsigned*)(sm + AUXO + 5632);

    if (tid < 128) {
        s_sqc[tid]  = g_sq[colBase + tid];  s_labc[tid] = labels[colBase + tid];
        s_sqr[tid]  = g_sq[rowBase + tid];  s_labr[tid] = labels[rowBase + tid];
        s_hp2r[tid] = g_hp2[rowBase + tid]; s_hpBr[tid] = g_hpB2[rowBase + tid];
        s_hp2c[tid] = g_hp2[colBase + tid]; s_hpBc[tid] = g_hpB2[colBase + tid];
        shRmax[tid] = 0u; shRmin[tid] = __float_as_uint(BIGD2);
        shCmax[tid] = 0u; shCmin[tid] = __float_as_uint(BIGD2);
    }

    const __half* gsrc[4];
    uint32_t sdst[4];
    {
        const __half* tps[2] = {g_Ehi + (size_t)rowBase * d,
                                g_Ehi + (size_t)colBase * d};
#pragma unroll
        for (int j = 0; j < 4; j++) {
            int t = j >> 1;
            int w = ((j & 1) << 9) + tid;
            int r = w >> 3, ch = w & 7;
            gsrc[j] = tps[t] + (size_t)r * d + ch * 8;
            sdst[j] = sb + t * TILEB + swz(r, ch);
        }
    }

    int r0A = wm * 32 + (lane & 15);
    int cA  = lane >> 4;
    int r0B = wn * 32 + (lane & 7) + ((lane >> 4) & 1) * 8;
    int cB  = (lane >> 3) & 1;
    uint32_t aoff[4], boff[4];
#pragma unroll
    for (int s = 0; s < 4; s++) {
        aoff[s] = swz(r0A, 2 * s + cA);
        boff[s] = swz(r0B, 2 * s + cB);
    }

    float acc[2][4][4];
#pragma unroll
    for (int im = 0; im < 2; im++)
#pragma unroll
        for (int in = 0; in < 4; in++)
#pragma unroll
            for (int e = 0; e < 4; e++) acc[im][in][e] = 0.f;

    int NC = d / BK;   // 8

#pragma unroll
    for (int st = 0; st < 3; st++) {
#pragma unroll
        for (int j = 0; j < 4; j++) CP_ASYNC16(sdst[j] + st * STAGEB, gsrc[j] + st * BK);
        CP_COMMIT();
    }

    int cb = 0, ib = 3;
    for (int c = 0; c < NC; c++) {
        if (c + 3 <= NC)      { CP_WAIT2(); }
        else if (c + 2 <= NC) { CP_WAIT1(); }
        else                  { CP_WAIT0(); }
        __syncthreads();
        if (c + 3 < NC) {
            int k0 = (c + 3) * BK;
            uint32_t so = (uint32_t)ib * STAGEB;
#pragma unroll
            for (int j = 0; j < 4; j++) CP_ASYNC16(sdst[j] + so, gsrc[j] + k0);
            CP_COMMIT();
            ib = (ib + 1) & 3;
        }

        uint32_t base = sb + (uint32_t)cb * STAGEB;
#pragma unroll
        for (int h = 0; h < 2; h++) {
            uint32_t ah[2][2][4], bh[2][4][2];
#pragma unroll
            for (int s2 = 0; s2 < 2; s2++) {
                int s = 2 * h + s2;
#pragma unroll
                for (int im = 0; im < 2; im++) {
                    uint32_t aA = base + im * 2048 + aoff[s];
                    LDM4(ah[s2][im][0], ah[s2][im][1], ah[s2][im][2], ah[s2][im][3], aA);
                }
#pragma unroll
                for (int p = 0; p < 2; p++) {
                    uint32_t aB = base + TILEB + p * 2048 + boff[s];
                    LDM4(bh[s2][2 * p][0], bh[s2][2 * p][1],
                         bh[s2][2 * p + 1][0], bh[s2][2 * p + 1][1], aB);
                }
            }
#pragma unroll
            for (int s2 = 0; s2 < 2; s2++)
#pragma unroll
                for (int im = 0; im < 2; im++)
#pragma unroll
                    for (int in = 0; in < 4; in++)
                        MMA16816(acc[im][in], ah[s2][im], bh[s2][in][0], bh[s2][in][1]);
        }
        cb = (cb + 1) & 3;
    }

    // ---- epilogue: row-side ----
#pragma unroll
    for (int im = 0; im < 2; im++)
#pragma unroll
        for (int eh = 0; eh < 2; eh++) {
            int rloc = wm * 32 + im * 16 + (lane >> 2) + eh * 8;
            float sqr = s_sqr[rloc];
            int   labr = s_labr[rloc];
            float A = s_hp2r[rloc], B = s_hpBr[rloc];
            float mx = 0.f, mn = BIGD2;
#pragma unroll
            for (int in = 0; in < 4; in++)
#pragma unroll
                for (int ec = 0; ec < 2; ec++) {
                    int cloc = wn * 32 + in * 8 + (lane & 3) * 2 + ec;
                    float dot = acc[im][in][eh * 2 + ec];
                    float d2 = fmaxf(sqr + s_sqc[cloc] - 2.f * dot, 1e-12f);
                    if (labr != s_labc[cloc]) {
                        mx = fmaxf(mx, d2);
                        if (d2 > A && d2 < B) mn = fminf(mn, d2);
                    }
                }
            if (mx > 0.f) atomicMax(&shRmax[rloc], __float_as_uint(mx));
            if (mn < BIGD2) atomicMin(&shRmin[rloc], __float_as_uint(mn));
        }

    // ---- epilogue: col-side (skip on diagonal tiles) ----
    if (!diag) {
#pragma unroll
        for (int in = 0; in < 4; in++)
#pragma unroll
            for (int ec = 0; ec < 2; ec++) {
                int cloc = wn * 32 + in * 8 + (lane & 3) * 2 + ec;
                float sqc = s_sqc[cloc];
                int   labc = s_labc[cloc];
                float A = s_hp2c[cloc], B = s_hpBc[cloc];
                float mx = 0.f, mn = BIGD2;
#pragma unroll
                for (int im = 0; im < 2; im++)
#pragma unroll
                    for (int eh = 0; eh < 2; eh++) {
                        int rloc = wm * 32 + im * 16 + (lane >> 2) + eh * 8;
                        float dot = acc[im][in][eh * 2 + ec];
                        float d2 = fmaxf(s_sqr[rloc] + sqc - 2.f * dot, 1e-12f);
                        if (labc != s_labr[rloc]) {
                            mx = fmaxf(mx, d2);
                            if (d2 > A && d2 < B) mn = fminf(mn, d2);
                        }
                    }
                if (mx > 0.f) atomicMax(&shCmax[cloc], __float_as_uint(mx));
                if (mn < BIGD2) atomicMin(&shCmin[cloc], __float_as_uint(mn));
            }
    }

    __syncthreads();
    if (tid < 128) {
        if (shRmax[tid]) atomicMax(&g_hnfb[rowBase + tid], shRmax[tid]);
        if (shRmin[tid] != __float_as_uint(BIGD2)) {
            atomicMin(&g_hnsemi[rowBase + tid], shRmin[tid]);
            g_semiflag = 1;
        }
        if (!diag) {
            if (shCmax[tid]) atomicMax(&g_hnfb[colBase + tid], shCmax[tid]);
            if (shCmin[tid] != __float_as_uint(BIGD2)) {
                atomicMin(&g_hnsemi[colBase + tid], shCmin[tid]);
                g_semiflag = 1;
            }
        }
    }
}

// ---------------- kernel 4: finalize ----------------
__global__ void finalize_kernel(float* __restrict__ out, int n) {
    bool useSemi = (g_semiflag != 0);
    float sum = 0.f;
    int cnt = 0;
    for (int i = threadIdx.x; i < n; i += blockDim.x) {
        float hp = sqrtf(g_hp2[i]);
        unsigned hb = useSemi ? g_hnsemi[i] : g_hnfb[i];
        float hn = sqrtf(__uint_as_float(hb));
        float t = hp - hn + MARGIN;
        if (t < 0.f) t = 0.f;
        sum += t;
        if (t > 0.f) cnt++;
    }
    for (int o = 16; o; o >>= 1) {
        sum += __shfl_xor_sync(0xffffffffu, sum, o);
        cnt += __shfl_xor_sync(0xffffffffu, cnt, o);
    }
    __shared__ float wsum[32];
    __shared__ int wcnt[32];
    int lane = threadIdx.x & 31, w = threadIdx.x >> 5;
    if (lane == 0) { wsum[w] = sum; wcnt[w] = cnt; }
    __syncthreads();
    if (threadIdx.x == 0) {
        float s = 0.f; int c = 0;
        for (int k = 0; k < (int)(blockDim.x >> 5); k++) { s += wsum[k]; c += wcnt[k]; }
        out[0] = (c > 0) ? (s / (float)c) : 0.0f;
    }
}

// ---------------- launch ----------------
extern "C" void kernel_launch(void* const* d_in, const int* in_sizes, int n_in,
                              void* d_out, int out_size) {
    const float* E = (const float*)d_in[0];
    const int* labels = (const int*)d_in[1];
    int n = in_sizes[1];
    int d = in_sizes[0] / n;

    cudaFuncSetAttribute(gemm_kernel, cudaFuncAttributeMaxDynamicSharedMemorySize, SMEM_DYN);

    convsq_kernel<<<n / 8, 256>>>(E, d);                   // launch 0
    classlist_kernel<<<1, NB>>>(labels, n);                // launch 1
    hp_kernel<<<n, 256>>>(E, labels, n, d);                // launch 2
    int nb = n / 128;
    gemm_kernel<<<nb * (nb + 1) / 2, 512, SMEM_DYN>>>(labels, n, d);  // launch 3 (profiled)
    finalize_kernel<<<1, 1024>>>((float*)d_out, n);        // launch 4
}

// round 14
// speedup vs baseline: 1.0067x; 1.0067x over previous
#include <cuda_runtime.h>
#include <cuda_fp16.h>
#include <cstdint>
#include <math.h>

#define MAXN   4096
#define MAXD   512
#define NB     1024
#define MARGIN 0.3f
#define BIGD2  3.0e38f

// ---------------- scratch ----------------
__device__ __align__(16) __half g_Ehi[MAXN * MAXD];
__device__ float    g_sq[MAXN];
__device__ float    g_hp2[MAXN];
__device__ float    g_hpB2[MAXN];
__device__ unsigned g_hnfb[MAXN];
__device__ unsigned g_hnsemi[MAXN];
__device__ int      g_semiflag;
__device__ int      g_ccount[NB];
__device__ int      g_coff[NB];
__device__ int      g_clist[MAXN];

__device__ __forceinline__ uint32_t smem_u32(const void* p) {
    uint32_t a;
    asm("{ .reg .u64 t; cvta.to.shared.u64 t, %1; cvt.u32.u64 %0, t; }" : "=r"(a) : "l"(p));
    return a;
}

#define CP_ASYNC16(dst, src) \
    asm volatile("cp.async.cg.shared.global [%0], [%1], 16;" :: "r"(dst), "l"(src))
#define CP_COMMIT() asm volatile("cp.async.commit_group;")
#define CP_WAIT2()  asm volatile("cp.async.wait_group 2;")
#define CP_WAIT1()  asm volatile("cp.async.wait_group 1;")
#define CP_WAIT0()  asm volatile("cp.async.wait_group 0;")

#define LDM4(r0, r1, r2, r3, addr)                                              \
    asm volatile("ldmatrix.sync.aligned.m8n8.x4.shared.b16 {%0,%1,%2,%3}, [%4];" \
        : "=r"(r0), "=r"(r1), "=r"(r2), "=r"(r3) : "r"(addr))

#define MMA16816(c, a, b0, b1)                                                   \
    asm volatile("mma.sync.aligned.m16n8k16.row.col.f32.f16.f16.f32 "            \
        "{%0,%1,%2,%3},{%4,%5,%6,%7},{%8,%9},{%0,%1,%2,%3};"                     \
        : "+f"((c)[0]), "+f"((c)[1]), "+f"((c)[2]), "+f"((c)[3])                 \
        : "r"((a)[0]), "r"((a)[1]), "r"((a)[2]), "r"((a)[3]), "r"(b0), "r"(b1))

// ---------------- kernel 0: convert + row sq + per-row init (warp per row) ----------
__global__ void convsq_kernel(const float* __restrict__ E, int d) {
    int wid = threadIdx.x >> 5, lane = threadIdx.x & 31;
    int row = blockIdx.x * 8 + wid;
    const float4* p = (const float4*)(E + (size_t)row * d);
    int d4 = d >> 2;
    float s = 0.f;
    for (int c = lane; c < d4; c += 32) {
        float4 v = p[c];
        s += v.x * v.x + v.y * v.y + v.z * v.z + v.w * v.w;
        __half2 h01 = __halves2half2(__float2half(v.x), __float2half(v.y));
        __half2 h23 = __halves2half2(__float2half(v.z), __float2half(v.w));
        size_t o = (size_t)row * d + 4 * c;
        *(__half2*)(g_Ehi + o) = h01;
        *(__half2*)(g_Ehi + o + 2) = h23;
    }
    for (int o = 16; o; o >>= 1) s += __shfl_xor_sync(0xffffffffu, s, o);
    if (lane == 0) {
        g_sq[row] = s;
        g_hnfb[row] = 0u;
        g_hnsemi[row] = __float_as_uint(BIGD2);
        if (row == 0) g_semiflag = 0;
    }
}

// ---------------- kernel 1: hist + scan + fill (single block) ----------------
__global__ void classlist_kernel(const int* __restrict__ labels, int n) {
    __shared__ int cnt[NB];
    __shared__ int s[NB];
    __shared__ int cur[NB];
    int t = threadIdx.x;
    cnt[t] = 0;
    __syncthreads();
    for (int i = t; i < n; i += blockDim.x) atomicAdd(&cnt[labels[i] & (NB - 1)], 1);
    __syncthreads();
    int v = cnt[t];
    s[t] = v;
    for (int off = 1; off < NB; off <<= 1) {
        __syncthreads();
        int u = (t >= off) ? s[t - off] : 0;
        __syncthreads();
        s[t] += u;
    }
    __syncthreads();
    int excl = s[t] - v;
    g_coff[t] = excl;
    g_ccount[t] = v;
    cur[t] = excl;
    __syncthreads();
    for (int i = t; i < n; i += blockDim.x) {
        int c = labels[i] & (NB - 1);
        int pos = atomicAdd(&cur[c], 1);
        g_clist[pos] = i;
    }
}

// ---------------- kernel 2: exact fp32 hardest positive (block per anchor) ----------
__global__ void hp_kernel(const float* __restrict__ E, const int* __restrict__ labels,
                          int n, int d) {
    int anchor = blockIdx.x;
    int lid = threadIdx.x & 31, wid = threadIdx.x >> 5;
    int c = labels[anchor] & (NB - 1);
    const float4* ea = (const float4*)(E + (size_t)anchor * d);
    int dk4 = d >> 7;
    float4 a0[MAXD / 128];
#pragma unroll
    for (int j = 0; j < MAXD / 128; j++) if (j < dk4) a0[j] = ea[lid + 32 * j];
    int beg = g_coff[c], cnt = g_ccount[c];
    float sqa = g_sq[anchor];
    float maxd2 = 0.f;
    for (int t = wid; t < cnt; t += 4) {
        int m = g_clist[beg + t];
        const float4* em = (const float4*)(E + (size_t)m * d);
        float dot = 0.f;
#pragma unroll
        for (int j = 0; j < MAXD / 128; j++)
            if (j < dk4) {
                float4 b = em[lid + 32 * j];
                dot += a0[j].x * b.x + a0[j].y * b.y + a0[j].z * b.z + a0[j].w * b.w;
            }
        for (int o = 16; o; o >>= 1) dot += __shfl_xor_sync(0xffffffffu, dot, o);
        float d2 = sqa + g_sq[m] - 2.f * dot;
        maxd2 = fmaxf(maxd2, d2);
    }
    __shared__ float wmax[4];
    if (lid == 0) wmax[wid] = maxd2;
    __syncthreads();
    if (threadIdx.x == 0) {
        float h2 = fmaxf(fmaxf(fmaxf(wmax[0], wmax[1]), fmaxf(wmax[2], wmax[3])), 1e-12f);
        g_hp2[anchor] = h2;
        float hp = sqrtf(h2);
        g_hpB2[anchor] = (hp + MARGIN) * (hp + MARGIN);
    }
}

// ------- kernel 3: HMMA GEMM, 256 thr / 8 warps (32x64 warp tiles), 4-stage ---------
#define BK      64
#define TILEB   16384
#define STAGEB  (2 * TILEB)
#define NSTAGE  4
#define AUXO    (NSTAGE * STAGEB)
#define SMEM_DYN (AUXO + 6144)

__device__ __forceinline__ uint32_t swz(int r, int ch) {
    return (uint32_t)(r * 128 + ((ch ^ (r & 7)) << 4));
}

__global__ __launch_bounds__(256, 1) void gemm_kernel(const int* __restrict__ labels,
                                                      int n, int d) {
    extern __shared__ char sm[];
    uint32_t sb = smem_u32(sm);
    int tid = threadIdx.x, lane = tid & 31, wid = tid >> 5;
    int wm = wid >> 1, wn = wid & 1;      // 4x2 warp grid; warp tile 32x64

    int bid = blockIdx.x;
    int by = (int)((sqrtf(8.f * (float)bid + 1.f) - 1.f) * 0.5f);
    while ((by + 1) * (by + 2) / 2 <= bid) by++;
    while (by * (by + 1) / 2 > bid) by--;
    int bx = bid - by * (by + 1) / 2;
    int rowBase = by * 128, colBase = bx * 128;
    bool diag = (bx == by);

    float*    s_sqc  = (float*)(sm + AUXO);
    int*      s_labc = (int*)(sm + AUXO + 512);
    float*    s_sqr  = (float*)(sm + AUXO + 1024);
    int*      s_labr = (int*)(sm + AUXO + 1536);
    float*    s_hp2r = (float*)(sm + AUXO + 2048);
    float*    s_hpBr = (float*)(sm + AUXO + 2560);
    float*    s_hp2c = (float*)(sm + AUXO + 3072);
    float*    s_hpBc = (float*)(sm + AUXO + 3584);
    unsigned* shRmax = (unsigned*)(sm + AUXO + 4096);
    unsigned* shRmin = (unsigned*)(sm + AUXO + 4608);
    unsigned* shCmax = (unsigned*)(sm + AUXO + 5120);
    unsigned* shCmin = (unsigned*)(sm + AUXO + 5632);

    if (tid < 128) {
        s_sqc[tid]  = g_sq[colBase + tid];  s_labc[tid] = labels[colBase + tid];
        s_sqr[tid]  = g_sq[rowBase + tid];  s_labr[tid] = labels[rowBase + tid];
        s_hp2r[tid] = g_hp2[rowBase + tid]; s_hpBr[tid] = g_hpB2[rowBase + tid];
        s_hp2c[tid] = g_hp2[colBase + tid]; s_hpBc[tid] = g_hpB2[colBase + tid];
        shRmax[tid] = 0u; shRmin[tid] = __float_as_uint(BIGD2);
        shCmax[tid] = 0u; shCmin[tid] = __float_as_uint(BIGD2);
    }

    // cp.async: 2048 16B chunks per stage / 256 threads = 8 per thread
    const __half* gsrc[8];
    uint32_t sdst[8];
    {
        const __half* tps[2] = {g_Ehi + (size_t)rowBase * d,
                                g_Ehi + (size_t)colBase * d};
#pragma unroll
        for (int j = 0; j < 8; j++) {
            int t = j >> 2;
            int w = ((j & 3) << 8) + tid;      // 0..1023
            int r = w >> 3, ch = w & 7;
            gsrc[j] = tps[t] + (size_t)r * d + ch * 8;
            sdst[j] = sb + t * TILEB + swz(r, ch);
        }
    }

    int r0A = wm * 32 + (lane & 15);
    int cA  = lane >> 4;
    int r0B = wn * 64 + (lane & 7) + ((lane >> 4) & 1) * 8;
    int cB  = (lane >> 3) & 1;
    uint32_t aoff[4], boff[4];
#pragma unroll
    for (int s = 0; s < 4; s++) {
        aoff[s] = swz(r0A, 2 * s + cA);
        boff[s] = swz(r0B, 2 * s + cB);
    }

    float acc[2][8][4];
#pragma unroll
    for (int im = 0; im < 2; im++)
#pragma unroll
        for (int in = 0; in < 8; in++)
#pragma unroll
            for (int e = 0; e < 4; e++) acc[im][in][e] = 0.f;

    int NC = d / BK;   // 8

#pragma unroll
    for (int st = 0; st < 3; st++) {
#pragma unroll
        for (int j = 0; j < 8; j++) CP_ASYNC16(sdst[j] + st * STAGEB, gsrc[j] + st * BK);
        CP_COMMIT();
    }

    int cb = 0, ib = 3;
    for (int c = 0; c < NC; c++) {
        if (c + 3 <= NC)      { CP_WAIT2(); }
        else if (c + 2 <= NC) { CP_WAIT1(); }
        else                  { CP_WAIT0(); }
        __syncthreads();
        if (c + 3 < NC) {
            int k0 = (c + 3) * BK;
            uint32_t so = (uint32_t)ib * STAGEB;
#pragma unroll
            for (int j = 0; j < 8; j++) CP_ASYNC16(sdst[j] + so, gsrc[j] + k0);
            CP_COMMIT();
            ib = (ib + 1) & 3;
        }

        uint32_t base = sb + (uint32_t)cb * STAGEB;
#pragma unroll
        for (int h = 0; h < 2; h++) {       // two half-chunks of 2 k16-steps
            uint32_t ah[2][2][4], bh[2][8][2];
#pragma unroll
            for (int s2 = 0; s2 < 2; s2++) {
                int s = 2 * h + s2;
#pragma unroll
                for (int im = 0; im < 2; im++) {
                    uint32_t aA = base + im * 2048 + aoff[s];
                    LDM4(ah[s2][im][0], ah[s2][im][1], ah[s2][im][2], ah[s2][im][3], aA);
                }
#pragma unroll
                for (int p = 0; p < 4; p++) {
                    uint32_t aB = base + TILEB + p * 2048 + boff[s];
                    LDM4(bh[s2][2 * p][0], bh[s2][2 * p][1],
                         bh[s2][2 * p + 1][0], bh[s2][2 * p + 1][1], aB);
                }
            }
#pragma unroll
            for (int s2 = 0; s2 < 2; s2++)
#pragma unroll
                for (int im = 0; im < 2; im++)
#pragma unroll
                    for (int in = 0; in < 8; in++)
                        MMA16816(acc[im][in], ah[s2][im], bh[s2][in][0], bh[s2][in][1]);
        }
        cb = (cb + 1) & 3;
    }

    // ---- epilogue: row-side ----
#pragma unroll
    for (int im = 0; im < 2; im++)
#pragma unroll
        for (int eh = 0; eh < 2; eh++) {
            int rloc = wm * 32 + im * 16 + (lane >> 2) + eh * 8;
            float sqr = s_sqr[rloc];
            int   labr = s_labr[rloc];
            float A = s_hp2r[rloc], B = s_hpBr[rloc];
            float mx = 0.f, mn = BIGD2;
#pragma unroll
            for (int in = 0; in < 8; in++)
#pragma unroll
                for (int ec = 0; ec < 2; ec++) {
                    int cloc = wn * 64 + in * 8 + (lane & 3) * 2 + ec;
                    float dot = acc[im][in][eh * 2 + ec];
                    float d2 = fmaxf(sqr + s_sqc[cloc] - 2.f * dot, 1e-12f);
                    if (labr != s_labc[cloc]) {
                        mx = fmaxf(mx, d2);
                        if (d2 > A && d2 < B) mn = fminf(mn, d2);
                    }
                }
            if (mx > 0.f) atomicMax(&shRmax[rloc], __float_as_uint(mx));
            if (mn < BIGD2) atomicMin(&shRmin[rloc], __float_as_uint(mn));
        }

    // ---- epilogue: col-side (skip on diagonal tiles) ----
    if (!diag) {
#pragma unroll
        for (int in = 0; in < 8; in++)
#pragma unroll
            for (int ec = 0; ec < 2; ec++) {
                int cloc = wn * 64 + in * 8 + (lane & 3) * 2 + ec;
                float sqc = s_sqc[cloc];
                int   labc = s_labc[cloc];
                float A = s_hp2c[cloc], B = s_hpBc[cloc];
                float mx = 0.f, mn = BIGD2;
#pragma unroll
                for (int im = 0; im < 2; im++)
#pragma unroll
                    for (int eh = 0; eh < 2; eh++) {
                        int rloc = wm * 32 + im * 16 + (lane >> 2) + eh * 8;
                        float dot = acc[im][in][eh * 2 + ec];
                        float d2 = fmaxf(s_sqr[rloc] + sqc - 2.f * dot, 1e-12f);
                        if (labc != s_labr[rloc]) {
                            mx = fmaxf(mx, d2);
                            if (d2 > A && d2 < B) mn = fminf(mn, d2);
                        }
                    }
                if (mx > 0.f) atomicMax(&shCmax[cloc], __float_as_uint(mx));
                if (mn < BIGD2) atomicMin(&shCmin[cloc], __float_as_uint(mn));
            }
    }

    __syncthreads();
    if (tid < 128) {
        if (shRmax[tid]) atomicMax(&g_hnfb[rowBase + tid], shRmax[tid]);
        if (shRmin[tid] != __float_as_uint(BIGD2)) {
            atomicMin(&g_hnsemi[rowBase + tid], shRmin[tid]);
            g_semiflag = 1;
        }
        if (!diag) {
            if (shCmax[tid]) atomicMax(&g_hnfb[colBase + tid], shCmax[tid]);
            if (shCmin[tid] != __float_as_uint(BIGD2)) {
                atomicMin(&g_hnsemi[colBase + tid], shCmin[tid]);
                g_semiflag = 1;
            }
        }
    }
}

// ---------------- kernel 4: finalize ----------------
__global__ void finalize_kernel(float* __restrict__ out, int n) {
    bool useSemi = (g_semiflag != 0);
    float sum = 0.f;
    int cnt = 0;
    for (int i = threadIdx.x; i < n; i += blockDim.x) {
        float hp = sqrtf(g_hp2[i]);
        unsigned hb = useSemi ? g_hnsemi[i] : g_hnfb[i];
        float hn = sqrtf(__uint_as_float(hb));
        float t = hp - hn + MARGIN;
        if (t < 0.f) t = 0.f;
        sum += t;
        if (t > 0.f) cnt++;
    }
    for (int o = 16; o; o >>= 1) {
        sum += __shfl_xor_sync(0xffffffffu, sum, o);
        cnt += __shfl_xor_sync(0xffffffffu, cnt, o);
    }
    __shared__ float wsum[32];
    __shared__ int wcnt[32];
    int lane = threadIdx.x & 31, w = threadIdx.x >> 5;
    if (lane == 0) { wsum[w] = sum; wcnt[w] = cnt; }
    __syncthreads();
    if (threadIdx.x == 0) {
        float s = 0.f; int c = 0;
        for (int k = 0; k < (int)(blockDim.x >> 5); k++) { s += wsum[k]; c += wcnt[k]; }
        out[0] = (c > 0) ? (s / (float)c) : 0.0f;
    }
}

// ---------------- launch ----------------
extern "C" void kernel_launch(void* const* d_in, const int* in_sizes, int n_in,
                              void* d_out, int out_size) {
    const float* E = (const float*)d_in[0];
    const int* labels = (const int*)d_in[1];
    int n = in_sizes[1];
    int d = in_sizes[0] / n;

    cudaFuncSetAttribute(gemm_kernel, cudaFuncAttributeMaxDynamicSharedMemorySize, SMEM_DYN);

    convsq_kernel<<<n / 8, 256>>>(E, d);                   // launch 0
    classlist_kernel<<<1, NB>>>(labels, n);                // launch 1
    hp_kernel<<<n, 128>>>(E, labels, n, d);                // launch 2
    int nb = n / 128;
    gemm_kernel<<<nb * (nb + 1) / 2, 256, SMEM_DYN>>>(labels, n, d);  // launch 3 (profiled)
    finalize_kernel<<<1, 1024>>>((float*)d_out, n);        // launch 4
}

// round 15
// speedup vs baseline: 1.1275x; 1.1200x over previous
#include <cuda_runtime.h>
#include <cuda_fp16.h>
#include <cstdint>
#include <math.h>

#define MAXN   4096
#define MAXD   512
#define NB     1024
#define MARGIN 0.3f
#define BIGD2  3.0e38f

// ---------------- scratch ----------------
__device__ __align__(16) __half g_Ehi[MAXN * MAXD];
__device__ float    g_sq[MAXN];
__device__ float    g_hp2[MAXN];
__device__ float    g_hpB2[MAXN];
__device__ unsigned g_hnfb[MAXN];
__device__ unsigned g_hnsemi[MAXN];
__device__ int      g_semiflag;
__device__ int      g_ccount[NB];
__device__ int      g_coff[NB];
__device__ int      g_clist[MAXN];

__device__ __forceinline__ uint32_t smem_u32(const void* p) {
    uint32_t a;
    asm("{ .reg .u64 t; cvta.to.shared.u64 t, %1; cvt.u32.u64 %0, t; }" : "=r"(a) : "l"(p));
    return a;
}

#define CP_ASYNC16(dst, src) \
    asm volatile("cp.async.cg.shared.global [%0], [%1], 16;" :: "r"(dst), "l"(src))
#define CP_COMMIT() asm volatile("cp.async.commit_group;")
#define CP_WAIT1()  asm volatile("cp.async.wait_group 1;")
#define CP_WAIT0()  asm volatile("cp.async.wait_group 0;")

#define LDM4(r0, r1, r2, r3, addr)                                              \
    asm volatile("ldmatrix.sync.aligned.m8n8.x4.shared.b16 {%0,%1,%2,%3}, [%4];" \
        : "=r"(r0), "=r"(r1), "=r"(r2), "=r"(r3) : "r"(addr))

#define MMA16816(c, a, b0, b1)                                                   \
    asm volatile("mma.sync.aligned.m16n8k16.row.col.f32.f16.f16.f32 "            \
        "{%0,%1,%2,%3},{%4,%5,%6,%7},{%8,%9},{%0,%1,%2,%3};"                     \
        : "+f"((c)[0]), "+f"((c)[1]), "+f"((c)[2]), "+f"((c)[3])                 \
        : "r"((a)[0]), "r"((a)[1]), "r"((a)[2]), "r"((a)[3]), "r"(b0), "r"(b1))

// ------ kernel 0: fused [convert + row sq + init] (blocks 0..nconv-1) + classlist ----
__global__ void pre_kernel(const float* __restrict__ E, const int* __restrict__ labels,
                           int n, int d, int nconv) {
    if ((int)blockIdx.x < nconv) {
        // convsq: warp per row, 8 rows per block
        int wid = threadIdx.x >> 5, lane = threadIdx.x & 31;
        int row = blockIdx.x * 8 + wid;
        const float4* p = (const float4*)(E + (size_t)row * d);
        int d4 = d >> 2;
        float s = 0.f;
        for (int c = lane; c < d4; c += 32) {
            float4 v = p[c];
            s += v.x * v.x + v.y * v.y + v.z * v.z + v.w * v.w;
            __half2 h01 = __halves2half2(__float2half(v.x), __float2half(v.y));
            __half2 h23 = __halves2half2(__float2half(v.z), __float2half(v.w));
            size_t o = (size_t)row * d + 4 * c;
            *(__half2*)(g_Ehi + o) = h01;
            *(__half2*)(g_Ehi + o + 2) = h23;
        }
        for (int o = 16; o; o >>= 1) s += __shfl_xor_sync(0xffffffffu, s, o);
        if (lane == 0) {
            g_sq[row] = s;
            g_hnfb[row] = 0u;
            g_hnsemi[row] = __float_as_uint(BIGD2);
            if (row == 0) g_semiflag = 0;
        }
        return;
    }
    // classlist: hist + scan + fill with 256 threads (4 bins per thread)
    __shared__ int cnt[NB];
    __shared__ int cur[NB];
    __shared__ int wsums[8];
    __shared__ int woff[8];
    int t = threadIdx.x, lane = t & 31, w = t >> 5;
    for (int b = t; b < NB; b += 256) cnt[b] = 0;
    __syncthreads();
    for (int i = t; i < n; i += 256) atomicAdd(&cnt[labels[i] & (NB - 1)], 1);
    __syncthreads();
    int v0 = cnt[4 * t], v1 = cnt[4 * t + 1], v2 = cnt[4 * t + 2], v3 = cnt[4 * t + 3];
    int tsum = v0 + v1 + v2 + v3;
    int x = tsum;
#pragma unroll
    for (int o = 1; o < 32; o <<= 1) {
        int u = __shfl_up_sync(0xffffffffu, x, o);
        if (lane >= o) x += u;
    }
    if (lane == 31) wsums[w] = x;
    __syncthreads();
    if (t == 0) {
        int acc = 0;
        for (int k = 0; k < 8; k++) { woff[k] = acc; acc += wsums[k]; }
    }
    __syncthreads();
    int e0 = (x - tsum) + woff[w];
    int e1 = e0 + v0, e2 = e1 + v1, e3 = e2 + v2;
    g_coff[4 * t] = e0; g_coff[4 * t + 1] = e1; g_coff[4 * t + 2] = e2; g_coff[4 * t + 3] = e3;
    g_ccount[4 * t] = v0; g_ccount[4 * t + 1] = v1; g_ccount[4 * t + 2] = v2; g_ccount[4 * t + 3] = v3;
    cur[4 * t] = e0; cur[4 * t + 1] = e1; cur[4 * t + 2] = e2; cur[4 * t + 3] = e3;
    __syncthreads();
    for (int i = t; i < n; i += 256) {
        int c = labels[i] & (NB - 1);
        int pos = atomicAdd(&cur[c], 1);
        g_clist[pos] = i;
    }
}

// ---------------- kernel 1: exact fp32 hardest positive (block per anchor) ----------
__global__ void hp_kernel(const float* __restrict__ E, const int* __restrict__ labels,
                          int n, int d) {
    int anchor = blockIdx.x;
    int lid = threadIdx.x & 31, wid = threadIdx.x >> 5;
    int c = labels[anchor] & (NB - 1);
    const float4* ea = (const float4*)(E + (size_t)anchor * d);
    int dk4 = d >> 7;
    float4 a0[MAXD / 128];
#pragma unroll
    for (int j = 0; j < MAXD / 128; j++) if (j < dk4) a0[j] = ea[lid + 32 * j];
    int beg = g_coff[c], cnt = g_ccount[c];
    float sqa = g_sq[anchor];
    float maxd2 = 0.f;
    for (int t = wid; t < cnt; t += 4) {
        int m = g_clist[beg + t];
        const float4* em = (const float4*)(E + (size_t)m * d);
        float dot = 0.f;
#pragma unroll
        for (int j = 0; j < MAXD / 128; j++)
            if (j < dk4) {
                float4 b = em[lid + 32 * j];
                dot += a0[j].x * b.x + a0[j].y * b.y + a0[j].z * b.z + a0[j].w * b.w;
            }
        for (int o = 16; o; o >>= 1) dot += __shfl_xor_sync(0xffffffffu, dot, o);
        float d2 = sqa + g_sq[m] - 2.f * dot;
        maxd2 = fmaxf(maxd2, d2);
    }
    __shared__ float wmax[4];
    if (lid == 0) wmax[wid] = maxd2;
    __syncthreads();
    if (threadIdx.x == 0) {
        float h2 = fmaxf(fmaxf(fmaxf(wmax[0], wmax[1]), fmaxf(wmax[2], wmax[3])), 1e-12f);
        g_hp2[anchor] = h2;
        float hp = sqrtf(h2);
        g_hpB2[anchor] = (hp + MARGIN) * (hp + MARGIN);
    }
}

// ------- kernel 2: HMMA GEMM, BK=128 (256B rows), 3-stage pipeline, 4 chunks --------
#define BK      128                   // halves per k-chunk = 256 bytes
#define TILEB   32768                 // 128 rows * 256 B
#define STAGEB  (2 * TILEB)           // Ahi, Bhi = 64 KB
#define NSTAGE  3
#define AUXO    (NSTAGE * STAGEB)     // 196608
#define SMEM_DYN (AUXO + 6144)

__device__ __forceinline__ uint32_t swz256(int r, int c16) {   // c16 in 0..15
    int half = c16 >> 3, ch = c16 & 7;
    return (uint32_t)(r * 256 + half * 128 + ((ch ^ (r & 7)) << 4));
}

__global__ __launch_bounds__(512, 1) void gemm_kernel(const int* __restrict__ labels,
                                                      int n, int d) {
    extern __shared__ char sm[];
    uint32_t sb = smem_u32(sm);
    int tid = threadIdx.x, lane = tid & 31, wid = tid >> 5;
    int wm = wid >> 2, wn = wid & 3;   // 4x4 warp grid; warp tile 32x32

    int bid = blockIdx.x;
    int by = (int)((sqrtf(8.f * (float)bid + 1.f) - 1.f) * 0.5f);
    while ((by + 1) * (by + 2) / 2 <= bid) by++;
    while (by * (by + 1) / 2 > bid) by--;
    int bx = bid - by * (by + 1) / 2;
    int rowBase = by * 128, colBase = bx * 128;
    bool diag = (bx == by);

    float*    s_sqc  = (float*)(sm + AUXO);
    int*      s_labc = (int*)(sm + AUXO + 512);
    float*    s_sqr  = (float*)(sm + AUXO + 1024);
    int*      s_labr = (int*)(sm + AUXO + 1536);
    float*    s_hp2r = (float*)(sm + AUXO + 2048);
    float*    s_hpBr = (float*)(sm + AUXO + 2560);
    float*    s_hp2c = (float*)(sm + AUXO + 3072);
    float*    s_hpBc = (float*)(sm + AUXO + 3584);
    unsigned* shRmax = (unsigned*)(sm + AUXO + 4096);
    unsigned* shRmin = (unsigned*)(sm + AUXO + 4608);
    unsigned* shCmax = (unsigned*)(sm + AUXO + 5120);
    unsigned* shCmin = (unsigned*)(sm + AUXO + 5632);

    if (tid < 128) {
        s_sqc[tid]  = g_sq[colBase + tid];  s_labc[tid] = labels[colBase + tid];
        s_sqr[tid]  = g_sq[rowBase + tid];  s_labr[tid] = labels[rowBase + tid];
        s_hp2r[tid] = g_hp2[rowBase + tid]; s_hpBr[tid] = g_hpB2[rowBase + tid];
        s_hp2c[tid] = g_hp2[colBase + tid]; s_hpBc[tid] = g_hpB2[colBase + tid];
        shRmax[tid] = 0u; shRmin[tid] = __float_as_uint(BIGD2);
        shCmax[tid] = 0u; shCmin[tid] = __float_as_uint(BIGD2);
    }

    // cp.async: per stage 2 tiles x 2048 chunks(16B) / 512 threads = 8 per thread
    const __half* gsrc[8];
    uint32_t sdst[8];
    {
        const __half* tps[2] = {g_Ehi + (size_t)rowBase * d,
                                g_Ehi + (size_t)colBase * d};
#pragma unroll
        for (int j = 0; j < 8; j++) {
            int t = j >> 2;
            int w = ((j & 3) << 9) + tid;      // 0..2047
            int r = w >> 4, c16 = w & 15;
            gsrc[j] = tps[t] + (size_t)r * d + c16 * 8;
            sdst[j] = sb + t * TILEB + swz256(r, c16);
        }
    }

    // per-lane ldmatrix addresses: 8 k16-steps per chunk; step s uses chunk 2s+colsel.
    // aoff4[s] holds steps 0..3 (half 0); steps 4..7 add 128 bytes (half 1).
    int r0A = wm * 32 + (lane & 15);
    int cA  = lane >> 4;
    int r0B = wn * 32 + (lane & 7) + ((lane >> 4) & 1) * 8;
    int cB  = (lane >> 3) & 1;
    uint32_t aoff4[4], boff4[4];
#pragma unroll
    for (int s = 0; s < 4; s++) {
        aoff4[s] = swz256(r0A, 2 * s + cA);
        boff4[s] = swz256(r0B, 2 * s + cB);
    }

    float acc[2][4][4];
#pragma unroll
    for (int im = 0; im < 2; im++)
#pragma unroll
        for (int in = 0; in < 4; in++)
#pragma unroll
            for (int e = 0; e < 4; e++) acc[im][in][e] = 0.f;

    int NC = d / BK;   // 4

    // prologue: stages 0 and 1 (chunks 0, 1)
#pragma unroll
    for (int st = 0; st < 2; st++) {
#pragma unroll
        for (int j = 0; j < 8; j++) CP_ASYNC16(sdst[j] + st * STAGEB, gsrc[j] + st * BK);
        CP_COMMIT();
    }

    int cb = 0, ib = 2;
    for (int c = 0; c < NC; c++) {
        if (c + 1 < NC) { CP_WAIT1(); } else { CP_WAIT0(); }
        __syncthreads();                       // stage cb visible; stage ib free
        if (c + 2 < NC) {
            int k0 = (c + 2) * BK;
            uint32_t so = (uint32_t)ib * STAGEB;
#pragma unroll
            for (int j = 0; j < 8; j++) CP_ASYNC16(sdst[j] + so, gsrc[j] + k0);
            CP_COMMIT();
            ib = (ib == 2) ? 0 : ib + 1;
        }

        uint32_t base = sb + (uint32_t)cb * STAGEB;
#pragma unroll
        for (int h = 0; h < 4; h++) {          // four half-chunks of 2 k16-steps
            uint32_t ah[2][2][4], bh[2][4][2];
#pragma unroll
            for (int s2 = 0; s2 < 2; s2++) {
                int s = 2 * h + s2;
                uint32_t ao = aoff4[s & 3] + ((s >> 2) << 7);
                uint32_t bo = boff4[s & 3] + ((s >> 2) << 7);
#pragma unroll
                for (int im = 0; im < 2; im++) {
                    uint32_t aA = base + im * 4096 + ao;   // 16 rows * 256 B
                    LDM4(ah[s2][im][0], ah[s2][im][1], ah[s2][im][2], ah[s2][im][3], aA);
                }
#pragma unroll
                for (int p = 0; p < 2; p++) {
                    uint32_t aB = base + TILEB + p * 4096 + bo;
                    LDM4(bh[s2][2 * p][0], bh[s2][2 * p][1],
                         bh[s2][2 * p + 1][0], bh[s2][2 * p + 1][1], aB);
                }
            }
#pragma unroll
            for (int s2 = 0; s2 < 2; s2++)
#pragma unroll
                for (int im = 0; im < 2; im++)
#pragma unroll
                    for (int in = 0; in < 4; in++)
                        MMA16816(acc[im][in], ah[s2][im], bh[s2][in][0], bh[s2][in][1]);
        }
        cb = (cb == 2) ? 0 : cb + 1;
    }

    // ---- epilogue: row-side ----
#pragma unroll
    for (int im = 0; im < 2; im++)
#pragma unroll
        for (int eh = 0; eh < 2; eh++) {
            int rloc = wm * 32 + im * 16 + (lane >> 2) + eh * 8;
            float sqr = s_sqr[rloc];
            int   labr = s_labr[rloc];
            float A = s_hp2r[rloc], B = s_hpBr[rloc];
            float mx = 0.f, mn = BIGD2;
#pragma unroll
            for (int in = 0; in < 4; in++)
#pragma unroll
                for (int ec = 0; ec < 2; ec++) {
                    int cloc = wn * 32 + in * 8 + (lane & 3) * 2 + ec;
                    float dot = acc[im][in][eh * 2 + ec];
                    float d2 = fmaxf(sqr + s_sqc[cloc] - 2.f * dot, 1e-12f);
                    if (labr != s_labc[cloc]) {
                        mx = fmaxf(mx, d2);
                        if (d2 > A && d2 < B) mn = fminf(mn, d2);
                    }
                }
            if (mx > 0.f) atomicMax(&shRmax[rloc], __float_as_uint(mx));
            if (mn < BIGD2) atomicMin(&shRmin[rloc], __float_as_uint(mn));
        }

    // ---- epilogue: col-side (skip on diagonal tiles) ----
    if (!diag) {
#pragma unroll
        for (int in = 0; in < 4; in++)
#pragma unroll
            for (int ec = 0; ec < 2; ec++) {
                int cloc = wn * 32 + in * 8 + (lane & 3) * 2 + ec;
                float sqc = s_sqc[cloc];
                int   labc = s_labc[cloc];
                float A = s_hp2c[cloc], B = s_hpBc[cloc];
                float mx = 0.f, mn = BIGD2;
#pragma unroll
                for (int im = 0; im < 2; im++)
#pragma unroll
                    for (int eh = 0; eh < 2; eh++) {
                        int rloc = wm * 32 + im * 16 + (lane >> 2) + eh * 8;
                        float dot = acc[im][in][eh * 2 + ec];
                        float d2 = fmaxf(s_sqr[rloc] + sqc - 2.f * dot, 1e-12f);
                        if (labc != s_labr[rloc]) {
                            mx = fmaxf(mx, d2);
                            if (d2 > A && d2 < B) mn = fminf(mn, d2);
                        }
                    }
                if (mx > 0.f) atomicMax(&shCmax[cloc], __float_as_uint(mx));
                if (mn < BIGD2) atomicMin(&shCmin[cloc], __float_as_uint(mn));
            }
    }

    __syncthreads();
    if (tid < 128) {
        if (shRmax[tid]) atomicMax(&g_hnfb[rowBase + tid], shRmax[tid]);
        if (shRmin[tid] != __float_as_uint(BIGD2)) {
            atomicMin(&g_hnsemi[rowBase + tid], shRmin[tid]);
            g_semiflag = 1;
        }
        if (!diag) {
            if (shCmax[tid]) atomicMax(&g_hnfb[colBase + tid], shCmax[tid]);
            if (shCmin[tid] != __float_as_uint(BIGD2)) {
                atomicMin(&g_hnsemi[colBase + tid], shCmin[tid]);
                g_semiflag = 1;
            }
        }
    }
}

// ---------------- kernel 3: finalize ----------------
__global__ void finalize_kernel(float* __restrict__ out, int n) {
    bool useSemi = (g_semiflag != 0);
    float sum = 0.f;
    int cnt = 0;
    for (int i = threadIdx.x; i < n; i += blockDim.x) {
        float hp = sqrtf(g_hp2[i]);
        unsigned hb = useSemi ? g_hnsemi[i] : g_hnfb[i];
        float hn = sqrtf(__uint_as_float(hb));
        float t = hp - hn + MARGIN;
        if (t < 0.f) t = 0.f;
        sum += t;
        if (t > 0.f) cnt++;
    }
    for (int o = 16; o; o >>= 1) {
        sum += __shfl_xor_sync(0xffffffffu, sum, o);
        cnt += __shfl_xor_sync(0xffffffffu, cnt, o);
    }
    __shared__ float wsum[32];
    __shared__ int wcnt[32];
    int lane = threadIdx.x & 31, w = threadIdx.x >> 5;
    if (lane == 0) { wsum[w] = sum; wcnt[w] = cnt; }
    __syncthreads();
    if (threadIdx.x == 0) {
        float s = 0.f; int c = 0;
        for (int k = 0; k < (int)(blockDim.x >> 5); k++) { s += wsum[k]; c += wcnt[k]; }
        out[0] = (c > 0) ? (s / (float)c) : 0.0f;
    }
}

// ---------------- launch ----------------
extern "C" void kernel_launch(void* const* d_in, const int* in_sizes, int n_in,
                              void* d_out, int out_size) {
    const float* E = (const float*)d_in[0];
    const int* labels = (const int*)d_in[1];
    int n = in_sizes[1];
    int d = in_sizes[0] / n;

    cudaFuncSetAttribute(gemm_kernel, cudaFuncAttributeMaxDynamicSharedMemorySize, SMEM_DYN);

    int nconv = n / 8;
    pre_kernel<<<nconv + 1, 256>>>(E, labels, n, d, nconv);      // launch 0 (fused)
    hp_kernel<<<n, 128>>>(E, labels, n, d);                      // launch 1
    int nb = n / 128;
    gemm_kernel<<<nb * (nb + 1) / 2, 512, SMEM_DYN>>>(labels, n, d);  // launch 2
    finalize_kernel<<<1, 1024>>>((float*)d_out, n);              // launch 3
}

// round 16
// speedup vs baseline: 1.1281x; 1.0005x over previous
#include <cuda_runtime.h>
#include <cuda_fp16.h>
#include <cstdint>
#include <math.h>

#define MAXN   4096
#define MAXD   512
#define NB     1024
#define MARGIN 0.3f
#define BIGD2  3.0e38f

// ---------------- scratch ----------------
__device__ __align__(16) __half g_Ehi[MAXN * MAXD];
__device__ float    g_sq[MAXN];
__device__ float    g_hp2[MAXN];
__device__ float    g_hpB2[MAXN];
__device__ unsigned g_hnfb[MAXN];
__device__ unsigned g_hnsemi[MAXN];
__device__ int      g_semiflag;
__device__ int      g_ccount[NB];
__device__ int      g_coff[NB];
__device__ int      g_clist[MAXN];
__device__ float    g_psum[64];
__device__ int      g_pcnt[64];
__device__ int      g_fdone;

__device__ __forceinline__ uint32_t smem_u32(const void* p) {
    uint32_t a;
    asm("{ .reg .u64 t; cvta.to.shared.u64 t, %1; cvt.u32.u64 %0, t; }" : "=r"(a) : "l"(p));
    return a;
}

#define CP_ASYNC16(dst, src) \
    asm volatile("cp.async.cg.shared.global [%0], [%1], 16;" :: "r"(dst), "l"(src))
#define CP_COMMIT() asm volatile("cp.async.commit_group;")
#define CP_WAIT1()  asm volatile("cp.async.wait_group 1;")
#define CP_WAIT0()  asm volatile("cp.async.wait_group 0;")

#define LDM4(r0, r1, r2, r3, addr)                                              \
    asm volatile("ldmatrix.sync.aligned.m8n8.x4.shared.b16 {%0,%1,%2,%3}, [%4];" \
        : "=r"(r0), "=r"(r1), "=r"(r2), "=r"(r3) : "r"(addr))

#define MMA16816(c, a, b0, b1)                                                   \
    asm volatile("mma.sync.aligned.m16n8k16.row.col.f32.f16.f16.f32 "            \
        "{%0,%1,%2,%3},{%4,%5,%6,%7},{%8,%9},{%0,%1,%2,%3};"                     \
        : "+f"((c)[0]), "+f"((c)[1]), "+f"((c)[2]), "+f"((c)[3])                 \
        : "r"((a)[0]), "r"((a)[1]), "r"((a)[2]), "r"((a)[3]), "r"(b0), "r"(b1))

// ------ kernel 0: fused [convert + row sq + init] (blocks 0..nconv-1) + classlist ----
__global__ void pre_kernel(const float* __restrict__ E, const int* __restrict__ labels,
                           int n, int d, int nconv) {
    if ((int)blockIdx.x < nconv) {
        int wid = threadIdx.x >> 5, lane = threadIdx.x & 31;
        int row = blockIdx.x * 8 + wid;
        const float4* p = (const float4*)(E + (size_t)row * d);
        int d4 = d >> 2;
        float s = 0.f;
        for (int c = lane; c < d4; c += 32) {
            float4 v = p[c];
            s += v.x * v.x + v.y * v.y + v.z * v.z + v.w * v.w;
            __half2 h01 = __halves2half2(__float2half(v.x), __float2half(v.y));
            __half2 h23 = __halves2half2(__float2half(v.z), __float2half(v.w));
            size_t o = (size_t)row * d + 4 * c;
            *(__half2*)(g_Ehi + o) = h01;
            *(__half2*)(g_Ehi + o + 2) = h23;
        }
        for (int o = 16; o; o >>= 1) s += __shfl_xor_sync(0xffffffffu, s, o);
        if (lane == 0) {
            g_sq[row] = s;
            g_hnfb[row] = 0u;
            g_hnsemi[row] = __float_as_uint(BIGD2);
            if (row == 0) { g_semiflag = 0; g_fdone = 0; }
        }
        return;
    }
    // classlist: hist + scan + fill with 256 threads (4 bins per thread)
    __shared__ int cnt[NB];
    __shared__ int cur[NB];
    __shared__ int wsums[8];
    __shared__ int woff[8];
    int t = threadIdx.x, lane = t & 31, w = t >> 5;
    for (int b = t; b < NB; b += 256) cnt[b] = 0;
    __syncthreads();
    for (int i = t; i < n; i += 256) atomicAdd(&cnt[labels[i] & (NB - 1)], 1);
    __syncthreads();
    int v0 = cnt[4 * t], v1 = cnt[4 * t + 1], v2 = cnt[4 * t + 2], v3 = cnt[4 * t + 3];
    int tsum = v0 + v1 + v2 + v3;
    int x = tsum;
#pragma unroll
    for (int o = 1; o < 32; o <<= 1) {
        int u = __shfl_up_sync(0xffffffffu, x, o);
        if (lane >= o) x += u;
    }
    if (lane == 31) wsums[w] = x;
    __syncthreads();
    if (t == 0) {
        int acc = 0;
        for (int k = 0; k < 8; k++) { woff[k] = acc; acc += wsums[k]; }
    }
    __syncthreads();
    int e0 = (x - tsum) + woff[w];
    int e1 = e0 + v0, e2 = e1 + v1, e3 = e2 + v2;
    g_coff[4 * t] = e0; g_coff[4 * t + 1] = e1; g_coff[4 * t + 2] = e2; g_coff[4 * t + 3] = e3;
    g_ccount[4 * t] = v0; g_ccount[4 * t + 1] = v1; g_ccount[4 * t + 2] = v2; g_ccount[4 * t + 3] = v3;
    cur[4 * t] = e0; cur[4 * t + 1] = e1; cur[4 * t + 2] = e2; cur[4 * t + 3] = e3;
    __syncthreads();
    for (int i = t; i < n; i += 256) {
        int c = labels[i] & (NB - 1);
        int pos = atomicAdd(&cur[c], 1);
        g_clist[pos] = i;
    }
}

// ---------------- kernel 1: exact fp32 hardest positive (block per anchor) ----------
__global__ void hp_kernel(const float* __restrict__ E, const int* __restrict__ labels,
                          int n, int d) {
    int anchor = blockIdx.x;
    int lid = threadIdx.x & 31, wid = threadIdx.x >> 5;
    int c = labels[anchor] & (NB - 1);
    const float4* ea = (const float4*)(E + (size_t)anchor * d);
    int dk4 = d >> 7;
    float4 a0[MAXD / 128];
#pragma unroll
    for (int j = 0; j < MAXD / 128; j++) if (j < dk4) a0[j] = ea[lid + 32 * j];
    int beg = g_coff[c], cnt = g_ccount[c];
    float sqa = g_sq[anchor];
    float maxd2 = 0.f;
    for (int t = wid; t < cnt; t += 4) {
        int m = g_clist[beg + t];
        const float4* em = (const float4*)(E + (size_t)m * d);
        float dot = 0.f;
#pragma unroll
        for (int j = 0; j < MAXD / 128; j++)
            if (j < dk4) {
                float4 b = em[lid + 32 * j];
                dot += a0[j].x * b.x + a0[j].y * b.y + a0[j].z * b.z + a0[j].w * b.w;
            }
        for (int o = 16; o; o >>= 1) dot += __shfl_xor_sync(0xffffffffu, dot, o);
        float d2 = sqa + g_sq[m] - 2.f * dot;
        maxd2 = fmaxf(maxd2, d2);
    }
    __shared__ float wmax[4];
    if (lid == 0) wmax[wid] = maxd2;
    __syncthreads();
    if (threadIdx.x == 0) {
        float h2 = fmaxf(fmaxf(fmaxf(wmax[0], wmax[1]), fmaxf(wmax[2], wmax[3])), 1e-12f);
        g_hp2[anchor] = h2;
        float hp = sqrtf(h2);
        g_hpB2[anchor] = (hp + MARGIN) * (hp + MARGIN);
    }
}

// ------- kernel 2: HMMA GEMM, BK=128 (256B rows), 3-stage pipeline, 4 chunks --------
#define BK      128
#define TILEB   32768
#define STAGEB  (2 * TILEB)
#define NSTAGE  3
#define AUXO    (NSTAGE * STAGEB)
#define SMEM_DYN (AUXO + 6144)

__device__ __forceinline__ uint32_t swz256(int r, int c16) {
    int half = c16 >> 3, ch = c16 & 7;
    return (uint32_t)(r * 256 + half * 128 + ((ch ^ (r & 7)) << 4));
}

__global__ __launch_bounds__(512, 1) void gemm_kernel(const int* __restrict__ labels,
                                                      int n, int d) {
    extern __shared__ char sm[];
    uint32_t sb = smem_u32(sm);
    int tid = threadIdx.x, lane = tid & 31, wid = tid >> 5;
    int wm = wid >> 2, wn = wid & 3;

    int bid = blockIdx.x;
    int by = (int)((sqrtf(8.f * (float)bid + 1.f) - 1.f) * 0.5f);
    while ((by + 1) * (by + 2) / 2 <= bid) by++;
    while (by * (by + 1) / 2 > bid) by--;
    int bx = bid - by * (by + 1) / 2;
    int rowBase = by * 128, colBase = bx * 128;
    bool diag = (bx == by);

    float*    s_sqc  = (float*)(sm + AUXO);
    int*      s_labc = (int*)(sm + AUXO + 512);
    float*    s_sqr  = (float*)(sm + AUXO + 1024);
    int*      s_labr = (int*)(sm + AUXO + 1536);
    float*    s_hp2r = (float*)(sm + AUXO + 2048);
    float*    s_hpBr = (float*)(sm + AUXO + 2560);
    float*    s_hp2c = (float*)(sm + AUXO + 3072);
    float*    s_hpBc = (float*)(sm + AUXO + 3584);
    unsigned* shRmax = (unsigned*)(sm + AUXO + 4096);
    unsigned* shRmin = (unsigned*)(sm + AUXO + 4608);
    unsigned* shCmax = (unsigned*)(sm + AUXO + 5120);
    unsigned* shCmin = (unsigned*)(sm + AUXO + 5632);

    if (tid < 128) {
        s_sqc[tid]  = g_sq[colBase + tid];  s_labc[tid] = labels[colBase + tid];
        s_sqr[tid]  = g_sq[rowBase + tid];  s_labr[tid] = labels[rowBase + tid];
        s_hp2r[tid] = g_hp2[rowBase + tid]; s_hpBr[tid] = g_hpB2[rowBase + tid];
        s_hp2c[tid] = g_hp2[colBase + tid]; s_hpBc[tid] = g_hpB2[colBase + tid];
        shRmax[tid] = 0u; shRmin[tid] = __float_as_uint(BIGD2);
        shCmax[tid] = 0u; shCmin[tid] = __float_as_uint(BIGD2);
    }

    const __half* gsrc[8];
    uint32_t sdst[8];
    {
        const __half* tps[2] = {g_Ehi + (size_t)rowBase * d,
                                g_Ehi + (size_t)colBase * d};
#pragma unroll
        for (int j = 0; j < 8; j++) {
            int t = j >> 2;
            int w = ((j & 3) << 9) + tid;
            int r = w >> 4, c16 = w & 15;
            gsrc[j] = tps[t] + (size_t)r * d + c16 * 8;
            sdst[j] = sb + t * TILEB + swz256(r, c16);
        }
    }

    int r0A = wm * 32 + (lane & 15);
    int cA  = lane >> 4;
    int r0B = wn * 32 + (lane & 7) + ((lane >> 4) & 1) * 8;
    int cB  = (lane >> 3) & 1;
    uint32_t aoff4[4], boff4[4];
#pragma unroll
    for (int s = 0; s < 4; s++) {
        aoff4[s] = swz256(r0A, 2 * s + cA);
        boff4[s] = swz256(r0B, 2 * s + cB);
    }

    float acc[2][4][4];
#pragma unroll
    for (int im = 0; im < 2; im++)
#pragma unroll
        for (int in = 0; in < 4; in++)
#pragma unroll
            for (int e = 0; e < 4; e++) acc[im][in][e] = 0.f;

    int NC = d / BK;   // 4

#pragma unroll
    for (int st = 0; st < 2; st++) {
#pragma unroll
        for (int j = 0; j < 8; j++) CP_ASYNC16(sdst[j] + st * STAGEB, gsrc[j] + st * BK);
        CP_COMMIT();
    }

    int cb = 0, ib = 2;
    for (int c = 0; c < NC; c++) {
        if (c + 1 < NC) { CP_WAIT1(); } else { CP_WAIT0(); }
        __syncthreads();
        if (c + 2 < NC) {
            int k0 = (c + 2) * BK;
            uint32_t so = (uint32_t)ib * STAGEB;
#pragma unroll
            for (int j = 0; j < 8; j++) CP_ASYNC16(sdst[j] + so, gsrc[j] + k0);
            CP_COMMIT();
            ib = (ib == 2) ? 0 : ib + 1;
        }

        uint32_t base = sb + (uint32_t)cb * STAGEB;
#pragma unroll
        for (int h = 0; h < 4; h++) {
            uint32_t ah[2][2][4], bh[2][4][2];
#pragma unroll
            for (int s2 = 0; s2 < 2; s2++) {
                int s = 2 * h + s2;
                uint32_t ao = aoff4[s & 3] + ((s >> 2) << 7);
                uint32_t bo = boff4[s & 3] + ((s >> 2) << 7);
#pragma unroll
                for (int im = 0; im < 2; im++) {
                    uint32_t aA = base + im * 4096 + ao;
                    LDM4(ah[s2][im][0], ah[s2][im][1], ah[s2][im][2], ah[s2][im][3], aA);
                }
#pragma unroll
                for (int p = 0; p < 2; p++) {
                    uint32_t aB = base + TILEB + p * 4096 + bo;
                    LDM4(bh[s2][2 * p][0], bh[s2][2 * p][1],
                         bh[s2][2 * p + 1][0], bh[s2][2 * p + 1][1], aB);
                }
            }
#pragma unroll
            for (int s2 = 0; s2 < 2; s2++)
#pragma unroll
                for (int im = 0; im < 2; im++)
#pragma unroll
                    for (int in = 0; in < 4; in++)
                        MMA16816(acc[im][in], ah[s2][im], bh[s2][in][0], bh[s2][in][1]);
        }
        cb = (cb == 2) ? 0 : cb + 1;
    }

    // ---- epilogue: row-side ----
#pragma unroll
    for (int im = 0; im < 2; im++)
#pragma unroll
        for (int eh = 0; eh < 2; eh++) {
            int rloc = wm * 32 + im * 16 + (lane >> 2) + eh * 8;
            float sqr = s_sqr[rloc];
            int   labr = s_labr[rloc];
            float A = s_hp2r[rloc], B = s_hpBr[rloc];
            float mx = 0.f, mn = BIGD2;
#pragma unroll
            for (int in = 0; in < 4; in++)
#pragma unroll
                for (int ec = 0; ec < 2; ec++) {
                    int cloc = wn * 32 + in * 8 + (lane & 3) * 2 + ec;
                    float dot = acc[im][in][eh * 2 + ec];
                    float d2 = fmaxf(sqr + s_sqc[cloc] - 2.f * dot, 1e-12f);
                    if (labr != s_labc[cloc]) {
                        mx = fmaxf(mx, d2);
                        if (d2 > A && d2 < B) mn = fminf(mn, d2);
                    }
                }
            if (mx > 0.f) atomicMax(&shRmax[rloc], __float_as_uint(mx));
            if (mn < BIGD2) atomicMin(&shRmin[rloc], __float_as_uint(mn));
        }

    // ---- epilogue: col-side (skip on diagonal tiles) ----
    if (!diag) {
#pragma unroll
        for (int in = 0; in < 4; in++)
#pragma unroll
            for (int ec = 0; ec < 2; ec++) {
                int cloc = wn * 32 + in * 8 + (lane & 3) * 2 + ec;
                float sqc = s_sqc[cloc];
                int   labc = s_labc[cloc];
                float A = s_hp2c[cloc], B = s_hpBc[cloc];
                float mx = 0.f, mn = BIGD2;
#pragma unroll
                for (int im = 0; im < 2; im++)
#pragma unroll
                    for (int eh = 0; eh < 2; eh++) {
                        int rloc = wm * 32 + im * 16 + (lane >> 2) + eh * 8;
                        float dot = acc[im][in][eh * 2 + ec];
                        float d2 = fmaxf(s_sqr[rloc] + sqc - 2.f * dot, 1e-12f);
                        if (labc != s_labr[rloc]) {
                            mx = fmaxf(mx, d2);
                            if (d2 > A && d2 < B) mn = fminf(mn, d2);
                        }
                    }
                if (mx > 0.f) atomicMax(&shCmax[cloc], __float_as_uint(mx));
                if (mn < BIGD2) atomicMin(&shCmin[cloc], __float_as_uint(mn));
            }
    }

    __syncthreads();
    if (tid < 128) {
        if (shRmax[tid]) atomicMax(&g_hnfb[rowBase + tid], shRmax[tid]);
        if (shRmin[tid] != __float_as_uint(BIGD2)) {
            atomicMin(&g_hnsemi[rowBase + tid], shRmin[tid]);
            g_semiflag = 1;
        }
        if (!diag) {
            if (shCmax[tid]) atomicMax(&g_hnfb[colBase + tid], shCmax[tid]);
            if (shCmin[tid] != __float_as_uint(BIGD2)) {
                atomicMin(&g_hnsemi[colBase + tid], shCmin[tid]);
                g_semiflag = 1;
            }
        }
    }
}

// ------- kernel 3: multi-block finalize (threadFenceReduction pattern) --------------
__global__ void finalize_kernel(float* __restrict__ out, int n) {
    int blk = blockIdx.x, t = threadIdx.x;
    bool useSemi = (g_semiflag != 0);
    int i = blk * blockDim.x + t;
    float tr = 0.f;
    int c = 0;
    if (i < n) {
        float hp = sqrtf(g_hp2[i]);
        unsigned hb = useSemi ? g_hnsemi[i] : g_hnfb[i];
        float hn = sqrtf(__uint_as_float(hb));
        tr = hp - hn + MARGIN;
        if (tr < 0.f) tr = 0.f;
        if (tr > 0.f) c = 1;
    }
    float sum = tr;
    int cnt = c;
    for (int o = 16; o; o >>= 1) {
        sum += __shfl_xor_sync(0xffffffffu, sum, o);
        cnt += __shfl_xor_sync(0xffffffffu, cnt, o);
    }
    __shared__ float wsum[8];
    __shared__ int wcnt[8];
    int lane = t & 31, w = t >> 5;
    if (lane == 0) { wsum[w] = sum; wcnt[w] = cnt; }
    __syncthreads();
    if (t == 0) {
        float s = 0.f; int cc = 0;
        for (int k = 0; k < (int)(blockDim.x >> 5); k++) { s += wsum[k]; cc += wcnt[k]; }
        g_psum[blk] = s;
        g_pcnt[blk] = cc;
        __threadfence();
        int prev = atomicAdd(&g_fdone, 1);
        if (prev == (int)gridDim.x - 1) {
            float S = 0.f; int C = 0;
            for (int k = 0; k < (int)gridDim.x; k++) {
                S += *(volatile float*)&g_psum[k];
                C += *(volatile int*)&g_pcnt[k];
            }
            out[0] = (C > 0) ? (S / (float)C) : 0.0f;
        }
    }
}

// ---------------- launch ----------------
extern "C" void kernel_launch(void* const* d_in, const int* in_sizes, int n_in,
                              void* d_out, int out_size) {
    const float* E = (const float*)d_in[0];
    const int* labels = (const int*)d_in[1];
    int n = in_sizes[1];
    int d = in_sizes[0] / n;

    cudaFuncSetAttribute(gemm_kernel, cudaFuncAttributeMaxDynamicSharedMemorySize, SMEM_DYN);

    int nconv = n / 8;
    pre_kernel<<<nconv + 1, 256>>>(E, labels, n, d, nconv);           // launch 0
    hp_kernel<<<n, 128>>>(E, labels, n, d);                           // launch 1
    int nb = n / 128;
    gemm_kernel<<<nb * (nb + 1) / 2, 512, SMEM_DYN>>>(labels, n, d);  // launch 2
    finalize_kernel<<<(n + 255) / 256, 256>>>((float*)d_out, n);      // launch 3
}